// round 4
// baseline (speedup 1.0000x reference)
#include <cuda_runtime.h>

// Problem constants
#define B     4
#define N     8192
#define CIN   256
#define H     8
#define D     64
#define INNER 512
#define COUT  256
#define BH    (B*H)
#define NBLK  (N/64)     // 128 row-blocks per (b,h)

// Static device scratch (allocation-free rule: __device__ globals)
__device__ float g_part[(size_t)BH * NBLK * D * D];  // 64 MB: per-block dots partials
__device__ float g_dots[BH * D * D];                 // 512 KB
__device__ float g_wqe [B * INNER * CIN];            // 2 MB:  dots-folded Wq
__device__ float g_wfin[B * COUT * CIN];             // 1 MB:  fully folded weight

// ---- packed f32x2 helpers (Blackwell) ----
__device__ __forceinline__ unsigned long long pack2(float a) {
    unsigned long long r;
    asm("mov.b64 %0, {%1, %1};" : "=l"(r) : "f"(a));
    return r;
}
__device__ __forceinline__ void fma2(unsigned long long& c,
                                     unsigned long long a,
                                     unsigned long long w) {
    asm("fma.rn.f32x2 %0, %1, %2, %0;" : "+l"(c) : "l"(a), "l"(w));
}

// ============================================================================
// K1: per (b,h,64-row tile): K/V projection (64x128x256 GEMM) + instance-norm
//     + partial dots[64,64] accumulation, written to g_part.
// Block 256 threads (tx=16, ty=16). Thread owns 4 rows x 8 cols.
// Column ownership is INTERLEAVED: cols {2tx, 2tx+1} + 32*j, j=0..3
// -> all mainloop LDS.64 are bank-conflict-free (stride-2-word across 16 tx).
// ============================================================================
__global__ __launch_bounds__(256) void k1_proj_norm_dots(
    const float* __restrict__ ux,
    const float* __restrict__ Wk,
    const float* __restrict__ Wv)
{
    const int b = blockIdx.z, h = blockIdx.y, nb = blockIdx.x;
    const int bh = b * H + h;
    const int row0 = nb * 64;
    const int tid = threadIdx.x;
    const int tx = tid & 15, ty = tid >> 4;

    __shared__ float sbuf[64 * 130];   // aliased: [A|W] during mainloop, C after
    __shared__ float sStat[256];       // mean[128], rstd[128]
    float* sA = sbuf;                  // [32][65]  (A^T tile: [kk][row])
    float* sW = sbuf + 2080;           // [32][130] (W^T tile: [kk][col])
    float* sC = sbuf;                  // [64][130] result tile

    unsigned long long acc[4][4];
#pragma unroll
    for (int r = 0; r < 4; ++r)
#pragma unroll
        for (int j = 0; j < 4; ++j) acc[r][j] = 0ull;

    const float* uxb = ux + ((size_t)(b * N + row0)) * CIN;

    for (int kt = 0; kt < CIN; kt += 32) {
        __syncthreads();
#pragma unroll
        for (int l = 0; l < 8; ++l) {                 // A tile 64x32
            int idx = tid + l * 256;
            int r = idx >> 5, c = idx & 31;
            sA[c * 65 + r] = uxb[r * CIN + kt + c];
        }
#pragma unroll
        for (int l = 0; l < 16; ++l) {                // W tile 128x32 (Wk|Wv head h)
            int idx = tid + l * 256;
            int i = idx >> 5, c = idx & 31;
            const float* Wsrc = (i < 64) ? Wk : Wv;
            sW[c * 130 + i] = Wsrc[(h * 64 + (i & 63)) * CIN + kt + c];
        }
        __syncthreads();
#pragma unroll
        for (int kk = 0; kk < 32; ++kk) {
            const float* wrow = &sW[kk * 130 + 2 * tx];
            unsigned long long w0 = *reinterpret_cast<const unsigned long long*>(wrow);
            unsigned long long w1 = *reinterpret_cast<const unsigned long long*>(wrow + 32);
            unsigned long long w2 = *reinterpret_cast<const unsigned long long*>(wrow + 64);
            unsigned long long w3 = *reinterpret_cast<const unsigned long long*>(wrow + 96);
            const float* ap = &sA[kk * 65 + ty * 4];
#pragma unroll
            for (int r = 0; r < 4; ++r) {
                unsigned long long aa = pack2(ap[r]);
                fma2(acc[r][0], aa, w0);
                fma2(acc[r][1], aa, w1);
                fma2(acc[r][2], aa, w2);
                fma2(acc[r][3], aa, w3);
            }
        }
    }
    __syncthreads();

    // spill result tile to smem (cols 0..63 = k, 64..127 = v); conflict-free stores
#pragma unroll
    for (int r = 0; r < 4; ++r)
#pragma unroll
        for (int j = 0; j < 4; ++j)
            *reinterpret_cast<unsigned long long*>(
                &sC[(ty * 4 + r) * 130 + 2 * tx + 32 * j]) = acc[r][j];
    __syncthreads();

    // instance-norm stats per (row, group) over 64 channels
    if (tid < 128) {
        int row = tid & 63, grp = tid >> 6;
        const float* p = &sC[row * 130 + grp * 64];
        float s = 0.f, s2 = 0.f;
#pragma unroll
        for (int d = 0; d < 64; ++d) { float x = p[d]; s += x; s2 += x * x; }
        float mean = s * (1.f / 64.f);
        float var  = s2 * (1.f / 64.f) - mean * mean;
        sStat[tid]       = mean;
        sStat[128 + tid] = rsqrtf(var + 1e-5f);
    }
    __syncthreads();

    // normalize in place (stride-1 across threads: conflict-free)
    for (int idx = tid; idx < 64 * 128; idx += 256) {
        int row = idx >> 7, col = idx & 127, grp = col >> 6;
        float m  = sStat[grp * 64 + row];
        float rs = sStat[128 + grp * 64 + row];
        sC[row * 130 + col] = (sC[row * 130 + col] - m) * rs;
    }
    __syncthreads();

    // partial dots[d,e] += sum_n k[n,d] * v[n,e] over the 64 rows
    // thread owns d = ty*4+i (4), e in {2tx,2tx+1} and {2tx+32,2tx+33}
    unsigned long long dacc[4][2];
#pragma unroll
    for (int i = 0; i < 4; ++i) { dacc[i][0] = 0ull; dacc[i][1] = 0ull; }

    for (int nn = 0; nn < 64; ++nn) {
        const float* kp = &sC[nn * 130 + ty * 4];
        const float* vrow = &sC[nn * 130 + 64 + 2 * tx];
        unsigned long long v0 = *reinterpret_cast<const unsigned long long*>(vrow);
        unsigned long long v1 = *reinterpret_cast<const unsigned long long*>(vrow + 32);
#pragma unroll
        for (int i = 0; i < 4; ++i) {
            unsigned long long kk2 = pack2(kp[i]);
            fma2(dacc[i][0], kk2, v0);
            fma2(dacc[i][1], kk2, v1);
        }
    }

    float* pp = g_part + ((size_t)(bh * NBLK + nb)) * 4096;
#pragma unroll
    for (int i = 0; i < 4; ++i) {
        int d_ = ty * 4 + i;
        *reinterpret_cast<unsigned long long*>(&pp[d_ * 64 + 2 * tx])      = dacc[i][0];
        *reinterpret_cast<unsigned long long*>(&pp[d_ * 64 + 2 * tx + 32]) = dacc[i][1];
    }
}

// ============================================================================
// K2: reduce 128 partials -> g_dots (vectorized float4)
// 131072 outputs / 4 per thread = 32768 threads = 128 blocks
// ============================================================================
__global__ __launch_bounds__(256) void k2_reduce()
{
    int gid = blockIdx.x * 256 + threadIdx.x;        // 32768 float4 outputs
    int bh = gid >> 10, de4 = gid & 1023;
    const float4* p = reinterpret_cast<const float4*>(
        g_part + (size_t)bh * NBLK * 4096) + de4;
    float4 s = make_float4(0.f, 0.f, 0.f, 0.f);
#pragma unroll 8
    for (int q = 0; q < NBLK; ++q) {
        float4 v = p[(size_t)q * 1024];
        s.x += v.x; s.y += v.y; s.z += v.z; s.w += v.w;
    }
    reinterpret_cast<float4*>(g_dots)[gid] = s;
}

// ============================================================================
// K3a: Wq_eff[b, h*64+e, c] = (1/N) * sum_d dots[b,h,d,e] * Wq[h*64+d, c]
// grid (4 ctiles, H, B) = 128 blocks; thread owns 1 col, 16 e's.
// ============================================================================
__global__ __launch_bounds__(256) void k3_wqe(const float* __restrict__ Wq)
{
    const int c0 = blockIdx.x * 64, h = blockIdx.y, b = blockIdx.z;
    const int bh = b * H + h;
    const int tid = threadIdx.x;
    __shared__ float sd[4096];
    for (int idx = tid; idx < 4096; idx += 256)
        sd[idx] = g_dots[bh * 4096 + idx];
    __syncthreads();

    const int c = c0 + (tid & 63);
    const int e0 = (tid >> 6) * 16;
    float acc[16];
#pragma unroll
    for (int e = 0; e < 16; ++e) acc[e] = 0.f;
    for (int d = 0; d < 64; ++d) {
        float w = Wq[(h * 64 + d) * CIN + c];
        const float* sdr = &sd[d * 64 + e0];
#pragma unroll
        for (int e = 0; e < 16; ++e) acc[e] += sdr[e] * w;
    }
    const float invN = 1.0f / (float)N;
#pragma unroll
    for (int e = 0; e < 16; ++e)
        g_wqe[((size_t)b * INNER + h * 64 + e0 + e) * CIN + c] = acc[e] * invN;
}

// ============================================================================
// K3b: Wfinal[b,o,c] = sum_e Wo[o,e] * Wq_eff[b,e,c]
// grid (8 otiles, 8 ctiles, B) = 256 blocks; 32x32 tile, K=512 in 32-chunks.
// Thread owns c = c0+(tid&31), o's = o0+(tid>>5)*4 + {0..3}.
// ============================================================================
__global__ __launch_bounds__(256) void k3_wfin(const float* __restrict__ Wo)
{
    const int o0 = blockIdx.x * 32, c0 = blockIdx.y * 32, b = blockIdx.z;
    const int tid = threadIdx.x;
    __shared__ float sO[32 * 36];   // sO[e][o], padded (36 words: 16B-aligned rows)
    __shared__ float sQ[32 * 33];   // sQ[e][c]

    const int cl = tid & 31;
    const int ol = (tid >> 5) * 4;
    float acc[4] = {0.f, 0.f, 0.f, 0.f};

    for (int e0 = 0; e0 < INNER; e0 += 32) {
        __syncthreads();
        {
            int i = tid >> 5;           // 8 rows per pass, 4 passes
            int j = tid & 31;
#pragma unroll
            for (int p = 0; p < 4; ++p) {
                int r = i + p * 8;
                sO[j * 36 + r] = Wo[(o0 + r) * INNER + e0 + j];        // transpose
                sQ[r * 33 + j] = g_wqe[((size_t)b * INNER + e0 + r) * CIN + c0 + j];
            }
        }
        __syncthreads();
#pragma unroll
        for (int ee = 0; ee < 32; ++ee) {
            float q = sQ[ee * 33 + cl];
            const float4 wo4 = *reinterpret_cast<const float4*>(&sO[ee * 36 + ol]);
            acc[0] += wo4.x * q;
            acc[1] += wo4.y * q;
            acc[2] += wo4.z * q;
            acc[3] += wo4.w * q;
        }
    }
#pragma unroll
    for (int j = 0; j < 4; ++j)
        g_wfin[((size_t)b * COUT + o0 + ol + j) * CIN + c0 + cl] = acc[j];
}

// ============================================================================
// K4: out[b,n,o] = u_x[b,n,:] . Wfinal[b,o,:] + bo[o]
// Same tiling as K1 (64 rows x 128 cols, K-tile 32), interleaved columns.
// ============================================================================
__global__ __launch_bounds__(256) void k4_out(
    const float* __restrict__ ux,
    const float* __restrict__ bo,
    float* __restrict__ out)
{
    const int b = blockIdx.z;
    const int o0 = blockIdx.y * 128;
    const int row0 = blockIdx.x * 64;
    const int tid = threadIdx.x;
    const int tx = tid & 15, ty = tid >> 4;

    __shared__ float sbuf[2080 + 4160];
    float* sA = sbuf;          // [32][65]
    float* sW = sbuf + 2080;   // [32][130]

    unsigned long long acc[4][4];
#pragma unroll
    for (int r = 0; r < 4; ++r)
#pragma unroll
        for (int j = 0; j < 4; ++j) acc[r][j] = 0ull;

    const float* uxb = ux + ((size_t)(b * N + row0)) * CIN;
    const float* Wb  = g_wfin + (size_t)b * COUT * CIN + (size_t)o0 * CIN;

    for (int kt = 0; kt < CIN; kt += 32) {
        __syncthreads();
#pragma unroll
        for (int l = 0; l < 8; ++l) {
            int idx = tid + l * 256;
            int r = idx >> 5, c = idx & 31;
            sA[c * 65 + r] = uxb[r * CIN + kt + c];
        }
#pragma unroll
        for (int l = 0; l < 16; ++l) {
            int idx = tid + l * 256;
            int i = idx >> 5, c = idx & 31;
            sW[c * 130 + i] = Wb[i * CIN + kt + c];
        }
        __syncthreads();
#pragma unroll
        for (int kk = 0; kk < 32; ++kk) {
            const float* wrow = &sW[kk * 130 + 2 * tx];
            unsigned long long w0 = *reinterpret_cast<const unsigned long long*>(wrow);
            unsigned long long w1 = *reinterpret_cast<const unsigned long long*>(wrow + 32);
            unsigned long long w2 = *reinterpret_cast<const unsigned long long*>(wrow + 64);
            unsigned long long w3 = *reinterpret_cast<const unsigned long long*>(wrow + 96);
            const float* ap = &sA[kk * 65 + ty * 4];
#pragma unroll
            for (int r = 0; r < 4; ++r) {
                unsigned long long aa = pack2(ap[r]);
                fma2(acc[r][0], aa, w0);
                fma2(acc[r][1], aa, w1);
                fma2(acc[r][2], aa, w2);
                fma2(acc[r][3], aa, w3);
            }
        }
    }

    // epilogue: + bias, store (interleaved cols: o0 + 2tx + 32j)
#pragma unroll
    for (int r = 0; r < 4; ++r) {
        float* orow = out + ((size_t)(b * N) + row0 + ty * 4 + r) * COUT + o0;
#pragma unroll
        for (int j = 0; j < 4; ++j) {
            int col = 2 * tx + 32 * j;
            float2 v = *reinterpret_cast<float2*>(&acc[r][j]);
            float2 bb = *reinterpret_cast<const float2*>(&bo[o0 + col]);
            v.x += bb.x; v.y += bb.y;
            *reinterpret_cast<float2*>(&orow[col]) = v;
        }
    }
}

// ============================================================================
extern "C" void kernel_launch(void* const* d_in, const int* in_sizes, int n_in,
                              void* d_out, int out_size)
{
    const float* ux = (const float*)d_in[0];
    // d_in[1] = pos_x (unused by the reference computation)
    const float* Wq = (const float*)d_in[2];
    const float* Wk = (const float*)d_in[3];
    const float* Wv = (const float*)d_in[4];
    const float* Wo = (const float*)d_in[5];
    const float* bo = (const float*)d_in[6];
    float* out = (float*)d_out;

    k1_proj_norm_dots<<<dim3(NBLK, H, B), 256>>>(ux, Wk, Wv);
    k2_reduce<<<128, 256>>>();
    k3_wqe<<<dim3(4, H, B), 256>>>(Wq);
    k3_wfin<<<dim3(8, 8, B), 256>>>(Wo);
    k4_out<<<dim3(NBLK, 2, B), 256>>>(ux, bo, out);
}

// round 9
// speedup vs baseline: 1.8062x; 1.8062x over previous
#include <cuda_runtime.h>
#include <cuda_fp16.h>
#include <mma.h>
#include <cstdint>
using namespace nvcuda;

// Problem constants
#define B     4
#define N     8192
#define CIN   256
#define H     8
#define D     64
#define INNER 512
#define COUT  256
#define BH    (B*H)
#define NBLK  (N/64)       // 128 x 64-row tiles per (b,h)
#define KEXT  512          // hi(256) | lo(256)
#define LDA   72           // smem fp16 ld (bank-conflict-free for LDSM)
#define LDC   132          // smem fp32 C ld

// ---- device scratch ----
__device__ __align__(16) __half g_ah[(size_t)B * N * KEXT];      // 32 MB A ext (hi|lo)
__device__ __align__(16) __half g_wkv16[H * 128 * CIN];          // per-head [Wk|Wv] fp16
__device__ __align__(16) __half g_wf16[B * COUT * CIN];          // folded weight fp16
__device__ float g_part[(size_t)BH * NBLK * D * D];              // 64 MB dots partials
__device__ float g_dots[BH * D * D];
__device__ float g_wqe[B * INNER * CIN];
__device__ float g_wfin[B * COUT * CIN];

// ---- packed f32x2 helpers ----
__device__ __forceinline__ unsigned long long pack2(float a) {
    unsigned long long r;
    asm("mov.b64 %0, {%1, %1};" : "=l"(r) : "f"(a));
    return r;
}
__device__ __forceinline__ void fma2(unsigned long long& c,
                                     unsigned long long a, unsigned long long w) {
    asm("fma.rn.f32x2 %0, %1, %2, %0;" : "+l"(c) : "l"(a), "l"(w));
}
__device__ __forceinline__ uint32_t packh2(float a, float b) {
    __half2 h = __floats2half2_rn(a, b);
    return *reinterpret_cast<uint32_t*>(&h);
}

// ============ k0a: build A ext (hi|lo fp16) ============
__global__ __launch_bounds__(256) void k0a(const float* __restrict__ ux) {
    size_t i0 = (size_t)blockIdx.x * 256 + threadIdx.x;
    const float4* src = (const float4*)ux;
    for (size_t i = i0; i < (size_t)B * N * 64; i += 65536) {
        size_t row = i >> 6;
        int c4 = (int)(i & 63);
        float4 f = src[i];
        __half h0 = __float2half_rn(f.x), h1 = __float2half_rn(f.y);
        __half h2 = __float2half_rn(f.z), h3 = __float2half_rn(f.w);
        uint2 hi, lo;
        hi.x = (uint32_t)__half_as_ushort(h0) | ((uint32_t)__half_as_ushort(h1) << 16);
        hi.y = (uint32_t)__half_as_ushort(h2) | ((uint32_t)__half_as_ushort(h3) << 16);
        lo.x = packh2(f.x - __half2float(h0), f.y - __half2float(h1));
        lo.y = packh2(f.z - __half2float(h2), f.w - __half2float(h3));
        __half* dst = g_ah + row * KEXT + c4 * 4;
        *(uint2*)dst = hi;
        *(uint2*)(dst + CIN) = lo;
    }
}
// ============ k0w: [Wk|Wv] head images fp16 ============
__global__ __launch_bounds__(256) void k0w(const float* __restrict__ Wk,
                                           const float* __restrict__ Wv) {
    int h = blockIdx.x, tid = threadIdx.x;
    for (int i = tid; i < 8192; i += 256) {          // float4 per head
        int r = i >> 6, c = (i & 63) * 4;
        const float* src = (r < 64) ? (Wk + ((size_t)(h * 64 + r)) * CIN + c)
                                    : (Wv + ((size_t)(h * 64 + r - 64)) * CIN + c);
        float4 f = *(const float4*)src;
        uint2 v;
        v.x = packh2(f.x, f.y);
        v.y = packh2(f.z, f.w);
        *(uint2*)(g_wkv16 + (size_t)h * 32768 + r * CIN + c) = v;
    }
}
// ============ K1: wmma proj + fp32 norm + fp32 dots ============
__global__ __launch_bounds__(256) void k1w() {
    const int nb = blockIdx.x, h = blockIdx.y, b = blockIdx.z;
    const int bh = b * H + h, row0 = nb * 64;
    const int tid = threadIdx.x, wid = tid >> 5;
    const int wr = wid >> 1, wc = wid & 1;
    const int tx = tid & 15, ty = tid >> 4;

    __shared__ __align__(16) char smraw[64 * LDC * 4];   // 33792 B (aliased)
    __shared__ float sStat[256];
    __half* sA = (__half*)smraw;                 // [64][72]
    __half* sW = (__half*)(smraw + 9216);        // [128][72]
    float*  sC = (float*)smraw;                  // [64][132]

    wmma::fragment<wmma::accumulator, 16, 16, 16, float> c[4];
#pragma unroll
    for (int f = 0; f < 4; ++f) wmma::fill_fragment(c[f], 0.0f);

    const __half* abase = g_ah + ((size_t)(b * N + row0)) * KEXT;
    const __half* wbase = g_wkv16 + (size_t)h * 32768;

    for (int kt = 0; kt < KEXT; kt += 64) {
        int ktw = kt & (CIN - 1);
        __syncthreads();
#pragma unroll
        for (int l = 0; l < 2; ++l) {            // A tile 64x64 halves
            int idx = tid + l * 256;
            int r = idx >> 3, c8 = (idx & 7) * 8;
            *(uint4*)(sA + r * LDA + c8) = *(const uint4*)(abase + (size_t)r * KEXT + kt + c8);
        }
#pragma unroll
        for (int l = 0; l < 4; ++l) {            // W tile 128x64 halves
            int idx = tid + l * 256;
            int r = idx >> 3, c8 = (idx & 7) * 8;
            *(uint4*)(sW + r * LDA + c8) = *(const uint4*)(wbase + (size_t)r * CIN + ktw + c8);
        }
        __syncthreads();
#pragma unroll
        for (int ks = 0; ks < 4; ++ks) {
            wmma::fragment<wmma::matrix_a, 16, 16, 16, __half, wmma::row_major> a;
            wmma::load_matrix_sync(a, sA + (wr * 16) * LDA + ks * 16, LDA);
#pragma unroll
            for (int cf = 0; cf < 4; ++cf) {
                wmma::fragment<wmma::matrix_b, 16, 16, 16, __half, wmma::col_major> bf;
                wmma::load_matrix_sync(bf, sW + (wc * 64 + cf * 16) * LDA + ks * 16, LDA);
                wmma::mma_sync(c[cf], a, bf, c[cf]);
            }
        }
    }
    __syncthreads();
#pragma unroll
    for (int cf = 0; cf < 4; ++cf)
        wmma::store_matrix_sync(sC + (wr * 16) * LDC + wc * 64 + cf * 16, c[cf],
                                LDC, wmma::mem_row_major);
    __syncthreads();

    // instance-norm stats per (row, group) over 64 channels
    if (tid < 128) {
        int row = tid & 63, grp = tid >> 6;
        const float* p = &sC[row * LDC + grp * 64];
        float s = 0.f, s2 = 0.f;
#pragma unroll
        for (int d = 0; d < 64; ++d) { float x = p[d]; s += x; s2 += x * x; }
        float mean = s * (1.f / 64.f);
        float var = s2 * (1.f / 64.f) - mean * mean;
        sStat[tid] = mean;
        sStat[128 + tid] = rsqrtf(var + 1e-5f);
    }
    __syncthreads();
    for (int idx = tid; idx < 64 * 128; idx += 256) {
        int row = idx >> 7, col = idx & 127, grp = col >> 6;
        float m = sStat[grp * 64 + row];
        float rs = sStat[128 + grp * 64 + row];
        sC[row * LDC + col] = (sC[row * LDC + col] - m) * rs;
    }
    __syncthreads();

    // dots[d,e] += sum_n k[n,d]*v[n,e] over the 64 rows (fp32, f32x2)
    unsigned long long dacc[4][2];
#pragma unroll
    for (int i = 0; i < 4; ++i) { dacc[i][0] = 0ull; dacc[i][1] = 0ull; }
    for (int nn = 0; nn < 64; ++nn) {
        const float* kp = &sC[nn * LDC + ty * 4];
        const float* vrow = &sC[nn * LDC + 64 + 2 * tx];
        unsigned long long v0 = *(const unsigned long long*)vrow;
        unsigned long long v1 = *(const unsigned long long*)(vrow + 32);
#pragma unroll
        for (int i = 0; i < 4; ++i) {
            unsigned long long kk2 = pack2(kp[i]);
            fma2(dacc[i][0], kk2, v0);
            fma2(dacc[i][1], kk2, v1);
        }
    }
    float* pp = g_part + ((size_t)(bh * NBLK + nb)) * 4096;
#pragma unroll
    for (int i = 0; i < 4; ++i) {
        int d_ = ty * 4 + i;
        *(unsigned long long*)(&pp[d_ * 64 + 2 * tx]) = dacc[i][0];
        *(unsigned long long*)(&pp[d_ * 64 + 2 * tx + 32]) = dacc[i][1];
    }
}
// ============ k2: reduce 128 partials ============
__global__ __launch_bounds__(256) void k2_reduce() {
    int gid = blockIdx.x * 256 + threadIdx.x;        // 32768 float4 outputs
    int bh = gid >> 10, de4 = gid & 1023;
    const float4* p = (const float4*)(g_part + (size_t)bh * NBLK * 4096) + de4;
    float4 s = make_float4(0.f, 0.f, 0.f, 0.f);
#pragma unroll 8
    for (int q = 0; q < NBLK; ++q) {
        float4 v = p[(size_t)q * 1024];
        s.x += v.x; s.y += v.y; s.z += v.z; s.w += v.w;
    }
    ((float4*)g_dots)[gid] = s;
}
// ============ k3a: fold dots into Wq ============
__global__ __launch_bounds__(256) void k3_wqe(const float* __restrict__ Wq) {
    const int c0 = blockIdx.x * 64, h = blockIdx.y, b = blockIdx.z;
    const int bh = b * H + h, tid = threadIdx.x;
    __shared__ float sd[4096];
    for (int i = tid; i < 4096; i += 256) sd[i] = g_dots[bh * 4096 + i];
    __syncthreads();
    const int c = c0 + (tid & 63), e0 = (tid >> 6) * 16;
    float acc[16];
#pragma unroll
    for (int e = 0; e < 16; ++e) acc[e] = 0.f;
    for (int d = 0; d < 64; ++d) {
        float w = Wq[(h * 64 + d) * CIN + c];
        const float* sr = &sd[d * 64 + e0];
#pragma unroll
        for (int e = 0; e < 16; ++e) acc[e] += sr[e] * w;
    }
#pragma unroll
    for (int e = 0; e < 16; ++e)
        g_wqe[((size_t)b * INNER + h * 64 + e0 + e) * CIN + c] = acc[e] * (1.f / (float)N);
}
// ============ k3b: fold Wo ============
__global__ __launch_bounds__(256) void k3_wfin(const float* __restrict__ Wo) {
    const int o0 = blockIdx.x * 32, c0 = blockIdx.y * 32, b = blockIdx.z;
    const int tid = threadIdx.x;
    __shared__ float sO[32 * 36], sQ[32 * 33];
    const int cl = tid & 31, ol = (tid >> 5) * 4;
    float acc[4] = {0, 0, 0, 0};
    for (int e0 = 0; e0 < INNER; e0 += 32) {
        __syncthreads();
        int i = tid >> 5, j = tid & 31;
#pragma unroll
        for (int p = 0; p < 4; ++p) {
            int r = i + p * 8;
            sO[j * 36 + r] = Wo[(o0 + r) * INNER + e0 + j];
            sQ[r * 33 + j] = g_wqe[((size_t)b * INNER + e0 + r) * CIN + c0 + j];
        }
        __syncthreads();
#pragma unroll
        for (int e = 0; e < 32; ++e) {
            float q = sQ[e * 33 + cl];
            float4 w = *(const float4*)&sO[e * 36 + ol];
            acc[0] += w.x * q; acc[1] += w.y * q; acc[2] += w.z * q; acc[3] += w.w * q;
        }
    }
#pragma unroll
    for (int j = 0; j < 4; ++j)
        g_wfin[((size_t)b * COUT + o0 + ol + j) * CIN + c0 + cl] = acc[j];
}
// ============ k3w: Wfinal -> fp16 ============
__global__ __launch_bounds__(256) void k3w() {
    size_t i0 = (size_t)blockIdx.x * 256 + threadIdx.x;
    for (size_t i = i0; i < 65536; i += 16384) {
        float4 f = ((const float4*)g_wfin)[i];
        uint2 v;
        v.x = packh2(f.x, f.y);
        v.y = packh2(f.z, f.w);
        *(uint2*)(g_wf16 + i * 4) = v;
    }
}
// ============ K4: wmma output GEMM + bias ============
__global__ __launch_bounds__(256) void k4w(const float* __restrict__ bo,
                                           float* __restrict__ out) {
    const int nb = blockIdx.x, b = blockIdx.z;
    const int o0 = blockIdx.y * 128, row0 = nb * 64;
    const int tid = threadIdx.x, wid = tid >> 5;
    const int wr = wid >> 1, wc = wid & 1;

    __shared__ __align__(16) char smraw[64 * LDC * 4];
    __half* sA = (__half*)smraw;
    __half* sW = (__half*)(smraw + 9216);
    float*  sC = (float*)smraw;

    wmma::fragment<wmma::accumulator, 16, 16, 16, float> c[4];
#pragma unroll
    for (int f = 0; f < 4; ++f) wmma::fill_fragment(c[f], 0.0f);

    const __half* abase = g_ah + ((size_t)(b * N + row0)) * KEXT;
    const __half* wbase = g_wf16 + (size_t)b * COUT * CIN + (size_t)o0 * CIN;

    for (int kt = 0; kt < KEXT; kt += 64) {
        int ktw = kt & (CIN - 1);
        __syncthreads();
#pragma unroll
        for (int l = 0; l < 2; ++l) {
            int idx = tid + l * 256;
            int r = idx >> 3, c8 = (idx & 7) * 8;
            *(uint4*)(sA + r * LDA + c8) = *(const uint4*)(abase + (size_t)r * KEXT + kt + c8);
        }
#pragma unroll
        for (int l = 0; l < 4; ++l) {
            int idx = tid + l * 256;
            int r = idx >> 3, c8 = (idx & 7) * 8;
            *(uint4*)(sW + r * LDA + c8) = *(const uint4*)(wbase + (size_t)r * CIN + ktw + c8);
        }
        __syncthreads();
#pragma unroll
        for (int ks = 0; ks < 4; ++ks) {
            wmma::fragment<wmma::matrix_a, 16, 16, 16, __half, wmma::row_major> a;
            wmma::load_matrix_sync(a, sA + (wr * 16) * LDA + ks * 16, LDA);
#pragma unroll
            for (int cf = 0; cf < 4; ++cf) {
                wmma::fragment<wmma::matrix_b, 16, 16, 16, __half, wmma::col_major> bf;
                wmma::load_matrix_sync(bf, sW + (wc * 64 + cf * 16) * LDA + ks * 16, LDA);
                wmma::mma_sync(c[cf], a, bf, c[cf]);
            }
        }
    }
    __syncthreads();
#pragma unroll
    for (int cf = 0; cf < 4; ++cf)
        wmma::store_matrix_sync(sC + (wr * 16) * LDC + wc * 64 + cf * 16, c[cf],
                                LDC, wmma::mem_row_major);
    __syncthreads();

    // epilogue: bias + store (float4, coalesced)
    for (int idx = tid; idx < 2048; idx += 256) {
        int r = idx >> 5, c4 = (idx & 31) * 4;
        float4 v = *(const float4*)&sC[r * LDC + c4];
        float4 bb = *(const float4*)&bo[o0 + c4];
        v.x += bb.x; v.y += bb.y; v.z += bb.z; v.w += bb.w;
        *(float4*)(out + ((size_t)(b * N + row0 + r)) * COUT + o0 + c4) = v;
    }
}
// ============ launch ============
extern "C" void kernel_launch(void* const* d_in, const int* in_sizes, int n_in,
                              void* d_out, int out_size)
{
    const float* ux = (const float*)d_in[0];
    const float* Wq = (const float*)d_in[2];
    const float* Wk = (const float*)d_in[3];
    const float* Wv = (const float*)d_in[4];
    const float* Wo = (const float*)d_in[5];
    const float* bo = (const float*)d_in[6];
    float* out = (float*)d_out;

    k0a<<<256, 256>>>(ux);
    k0w<<<8, 256>>>(Wk, Wv);
    k1w<<<dim3(NBLK, H, B), 256>>>();
    k2_reduce<<<128, 256>>>();
    k3_wqe<<<dim3(4, H, B), 256>>>(Wq);
    k3_wfin<<<dim3(8, 8, B), 256>>>(Wo);
    k3w<<<64, 256>>>();
    k4w<<<dim3(NBLK, 2, B), 256>>>(bo, out);
}

// round 13
// speedup vs baseline: 1.8413x; 1.0194x over previous
#include <cuda_runtime.h>
#include <cuda_fp16.h>
#include <mma.h>
#include <cstdint>
using namespace nvcuda;

// Problem constants
#define B     4
#define N     8192
#define CIN   256
#define H     8
#define D     64
#define INNER 512
#define COUT  256
#define BH    (B*H)
#define KEXT  512          // hi(256) | lo(256)
#define LDA   72           // smem fp16 A ld
#define LDW   264          // smem fp16 persistent-W ld (row = 528B: conflict-free LDSM)
#define LDC   132          // smem fp32 C ld
#define TG1   8            // row-tiles per k1w block
#define TG4   4            // row-tiles per k4w block
#define NG1   16           // k1w tile-groups  (128 tiles / 8)

// smem layout (bytes)
#define OFF_AC   67584     // sW = [0,67584) ; sA/sC alias at 67584
#define OFF_STAT 101376
#define SMEM_K1  102400
#define SMEM_K4  101376

// ---- device scratch ----
__device__ __align__(16) __half g_ah[(size_t)B * N * KEXT];      // 32 MB A ext (hi|lo)
__device__ __align__(16) __half g_wkv16[H * 128 * CIN];          // per-head [Wk|Wv] fp16
__device__ __align__(16) __half g_wf16[B * COUT * CIN];          // folded weight fp16
__device__ float g_part[(size_t)BH * NG1 * D * D];               // 8 MB dots partials
__device__ float g_dots[BH * D * D];
__device__ float g_wqe[B * INNER * CIN];
__device__ float g_wfin[B * COUT * CIN];

// ---- packed f32x2 helpers ----
__device__ __forceinline__ unsigned long long pack2(float a) {
    unsigned long long r;
    asm("mov.b64 %0, {%1, %1};" : "=l"(r) : "f"(a));
    return r;
}
__device__ __forceinline__ void fma2(unsigned long long& c,
                                     unsigned long long a, unsigned long long w) {
    asm("fma.rn.f32x2 %0, %1, %2, %0;" : "+l"(c) : "l"(a), "l"(w));
}
__device__ __forceinline__ uint32_t packh2(float a, float b) {
    __half2 h = __floats2half2_rn(a, b);
    return *reinterpret_cast<uint32_t*>(&h);
}

// ============ k0a: build A ext (hi|lo fp16) ============
__global__ __launch_bounds__(256) void k0a(const float* __restrict__ ux) {
    size_t i0 = (size_t)blockIdx.x * 256 + threadIdx.x;
    const float4* src = (const float4*)ux;
    for (size_t i = i0; i < (size_t)B * N * 64; i += 65536) {
        size_t row = i >> 6;
        int c4 = (int)(i & 63);
        float4 f = src[i];
        __half h0 = __float2half_rn(f.x), h1 = __float2half_rn(f.y);
        __half h2 = __float2half_rn(f.z), h3 = __float2half_rn(f.w);
        uint2 hi, lo;
        hi.x = (uint32_t)__half_as_ushort(h0) | ((uint32_t)__half_as_ushort(h1) << 16);
        hi.y = (uint32_t)__half_as_ushort(h2) | ((uint32_t)__half_as_ushort(h3) << 16);
        lo.x = packh2(f.x - __half2float(h0), f.y - __half2float(h1));
        lo.y = packh2(f.z - __half2float(h2), f.w - __half2float(h3));
        __half* dst = g_ah + row * KEXT + c4 * 4;
        *(uint2*)dst = hi;
        *(uint2*)(dst + CIN) = lo;
    }
}
// ============ k0w: [Wk|Wv] head images fp16 ============
__global__ __launch_bounds__(256) void k0w(const float* __restrict__ Wk,
                                           const float* __restrict__ Wv) {
    int h = blockIdx.x, tid = threadIdx.x;
    for (int i = tid; i < 8192; i += 256) {
        int r = i >> 6, c = (i & 63) * 4;
        const float* src = (r < 64) ? (Wk + ((size_t)(h * 64 + r)) * CIN + c)
                                    : (Wv + ((size_t)(h * 64 + r - 64)) * CIN + c);
        float4 f = *(const float4*)src;
        uint2 v;
        v.x = packh2(f.x, f.y);
        v.y = packh2(f.z, f.w);
        *(uint2*)(g_wkv16 + (size_t)h * 32768 + r * CIN + c) = v;
    }
}
// ============ K1: persistent-W wmma proj + fp32 norm + fp32 dots (8 tiles) ============
__global__ __launch_bounds__(256, 2) void k1w() {
    const int g = blockIdx.x, h = blockIdx.y, b = blockIdx.z;
    const int bh = b * H + h;
    const int tid = threadIdx.x, wid = tid >> 5;
    const int wr = wid >> 1, wc = wid & 1;
    const int tx = tid & 15, ty = tid >> 4;

    extern __shared__ __align__(16) char sm[];
    __half* sW = (__half*)sm;                    // [128][264] persistent
    __half* sA = (__half*)(sm + OFF_AC);         // [64][72]   (aliased w/ sC)
    float*  sC = (float*)(sm + OFF_AC);          // [64][132]
    float*  sStat = (float*)(sm + OFF_STAT);     // [256]

    // load persistent W once (sync provided by first mainloop barrier)
    const __half* wsrc = g_wkv16 + (size_t)h * 32768;
    for (int i = tid; i < 4096; i += 256) {
        int r = i >> 5, c8 = (i & 31) * 8;
        *(uint4*)(sW + r * LDW + c8) = *(const uint4*)(wsrc + r * CIN + c8);
    }

    unsigned long long dacc[4][2];
#pragma unroll
    for (int i = 0; i < 4; ++i) { dacc[i][0] = 0ull; dacc[i][1] = 0ull; }

    for (int t = 0; t < TG1; ++t) {
        const int row0 = (g * TG1 + t) * 64;
        const __half* abase = g_ah + ((size_t)(b * N + row0)) * KEXT;

        wmma::fragment<wmma::accumulator, 16, 16, 16, float> c[4];
#pragma unroll
        for (int f = 0; f < 4; ++f) wmma::fill_fragment(c[f], 0.0f);

        for (int kt = 0; kt < KEXT; kt += 64) {
            int ktw = kt & (CIN - 1);
            __syncthreads();                     // protects sA/sC alias + sW on t==0,kt==0
#pragma unroll
            for (int l = 0; l < 2; ++l) {        // A tile 64x64
                int idx = tid + l * 256;
                int r = idx >> 3, c8 = (idx & 7) * 8;
                *(uint4*)(sA + r * LDA + c8) = *(const uint4*)(abase + (size_t)r * KEXT + kt + c8);
            }
            __syncthreads();
#pragma unroll
            for (int ks = 0; ks < 4; ++ks) {
                wmma::fragment<wmma::matrix_a, 16, 16, 16, __half, wmma::row_major> a;
                wmma::load_matrix_sync(a, sA + (wr * 16) * LDA + ks * 16, LDA);
#pragma unroll
                for (int cf = 0; cf < 4; ++cf) {
                    wmma::fragment<wmma::matrix_b, 16, 16, 16, __half, wmma::col_major> bf;
                    wmma::load_matrix_sync(bf, sW + (wc * 64 + cf * 16) * LDW + ktw + ks * 16, LDW);
                    wmma::mma_sync(c[cf], a, bf, c[cf]);
                }
            }
        }
        __syncthreads();
#pragma unroll
        for (int cf = 0; cf < 4; ++cf)
            wmma::store_matrix_sync(sC + (wr * 16) * LDC + wc * 64 + cf * 16, c[cf],
                                    LDC, wmma::mem_row_major);
        __syncthreads();

        // instance-norm stats per (row, group)
        if (tid < 128) {
            int row = tid & 63, grp = tid >> 6;
            const float* p = &sC[row * LDC + grp * 64];
            float s = 0.f, s2 = 0.f;
#pragma unroll
            for (int d = 0; d < 64; ++d) { float x = p[d]; s += x; s2 += x * x; }
            float mean = s * (1.f / 64.f);
            float var = s2 * (1.f / 64.f) - mean * mean;
            sStat[tid] = mean;
            sStat[128 + tid] = rsqrtf(var + 1e-5f);
        }
        __syncthreads();
        for (int idx = tid; idx < 64 * 128; idx += 256) {
            int row = idx >> 7, col = idx & 127, grp = col >> 6;
            float m = sStat[grp * 64 + row];
            float rs = sStat[128 + grp * 64 + row];
            sC[row * LDC + col] = (sC[row * LDC + col] - m) * rs;
        }
        __syncthreads();

        // dots accum over this tile's 64 rows (register-resident across tiles)
        for (int nn = 0; nn < 64; ++nn) {
            const float* kp = &sC[nn * LDC + ty * 4];
            const float* vrow = &sC[nn * LDC + 64 + 2 * tx];
            unsigned long long v0 = *(const unsigned long long*)vrow;
            unsigned long long v1 = *(const unsigned long long*)(vrow + 32);
#pragma unroll
            for (int i = 0; i < 4; ++i) {
                unsigned long long kk2 = pack2(kp[i]);
                fma2(dacc[i][0], kk2, v0);
                fma2(dacc[i][1], kk2, v1);
            }
        }
        // next tile's first barrier protects sC before sA overwrite
    }

    float* pp = g_part + ((size_t)(bh * NG1 + g)) * 4096;
#pragma unroll
    for (int i = 0; i < 4; ++i) {
        int d_ = ty * 4 + i;
        *(unsigned long long*)(&pp[d_ * 64 + 2 * tx]) = dacc[i][0];
        *(unsigned long long*)(&pp[d_ * 64 + 2 * tx + 32]) = dacc[i][1];
    }
}
// ============ k2: reduce 16 partials ============
__global__ __launch_bounds__(256) void k2_reduce() {
    int gid = blockIdx.x * 256 + threadIdx.x;        // 32768 float4 outputs
    int bh = gid >> 10, de4 = gid & 1023;
    const float4* p = (const float4*)(g_part + (size_t)bh * NG1 * 4096) + de4;
    float4 s = make_float4(0.f, 0.f, 0.f, 0.f);
#pragma unroll
    for (int q = 0; q < NG1; ++q) {
        float4 v = p[(size_t)q * 1024];
        s.x += v.x; s.y += v.y; s.z += v.z; s.w += v.w;
    }
    ((float4*)g_dots)[gid] = s;
}
// ============ k3a: fold dots into Wq ============
__global__ __launch_bounds__(256) void k3_wqe(const float* __restrict__ Wq) {
    const int c0 = blockIdx.x * 64, h = blockIdx.y, b = blockIdx.z;
    const int bh = b * H + h, tid = threadIdx.x;
    __shared__ float sd[4096];
    for (int i = tid; i < 4096; i += 256) sd[i] = g_dots[bh * 4096 + i];
    __syncthreads();
    const int c = c0 + (tid & 63), e0 = (tid >> 6) * 16;
    float acc[16];
#pragma unroll
    for (int e = 0; e < 16; ++e) acc[e] = 0.f;
    for (int d = 0; d < 64; ++d) {
        float w = Wq[(h * 64 + d) * CIN + c];
        const float* sr = &sd[d * 64 + e0];
#pragma unroll
        for (int e = 0; e < 16; ++e) acc[e] += sr[e] * w;
    }
#pragma unroll
    for (int e = 0; e < 16; ++e)
        g_wqe[((size_t)b * INNER + h * 64 + e0 + e) * CIN + c] = acc[e] * (1.f / (float)N);
}
// ============ k3b: fold Wo ============
__global__ __launch_bounds__(256) void k3_wfin(const float* __restrict__ Wo) {
    const int o0 = blockIdx.x * 32, c0 = blockIdx.y * 32, b = blockIdx.z;
    const int tid = threadIdx.x;
    __shared__ float sO[32 * 36], sQ[32 * 33];
    const int cl = tid & 31, ol = (tid >> 5) * 4;
    float acc[4] = {0, 0, 0, 0};
    for (int e0 = 0; e0 < INNER; e0 += 32) {
        __syncthreads();
        int i = tid >> 5, j = tid & 31;
#pragma unroll
        for (int p = 0; p < 4; ++p) {
            int r = i + p * 8;
            sO[j * 36 + r] = Wo[(o0 + r) * INNER + e0 + j];
            sQ[r * 33 + j] = g_wqe[((size_t)b * INNER + e0 + r) * CIN + c0 + j];
        }
        __syncthreads();
#pragma unroll
        for (int e = 0; e < 32; ++e) {
            float q = sQ[e * 33 + cl];
            float4 w = *(const float4*)&sO[e * 36 + ol];
            acc[0] += w.x * q; acc[1] += w.y * q; acc[2] += w.z * q; acc[3] += w.w * q;
        }
    }
#pragma unroll
    for (int j = 0; j < 4; ++j)
        g_wfin[((size_t)b * COUT + o0 + ol + j) * CIN + c0 + cl] = acc[j];
}
// ============ k3w: Wfinal -> fp16 ============
__global__ __launch_bounds__(256) void k3w() {
    size_t i0 = (size_t)blockIdx.x * 256 + threadIdx.x;
    for (size_t i = i0; i < 65536; i += 16384) {
        float4 f = ((const float4*)g_wfin)[i];
        uint2 v;
        v.x = packh2(f.x, f.y);
        v.y = packh2(f.z, f.w);
        *(uint2*)(g_wf16 + i * 4) = v;
    }
}
// ============ K4: persistent-W wmma output GEMM + bias (4 tiles) ============
__global__ __launch_bounds__(256, 2) void k4w(const float* __restrict__ bo,
                                              float* __restrict__ out) {
    const int g = blockIdx.x, b = blockIdx.z;
    const int o0 = blockIdx.y * 128;
    const int tid = threadIdx.x, wid = tid >> 5;
    const int wr = wid >> 1, wc = wid & 1;

    extern __shared__ __align__(16) char sm[];
    __half* sW = (__half*)sm;                    // [128][264] persistent
    __half* sA = (__half*)(sm + OFF_AC);
    float*  sC = (float*)(sm + OFF_AC);

    const __half* wsrc = g_wf16 + (size_t)b * COUT * CIN + (size_t)o0 * CIN;
    for (int i = tid; i < 4096; i += 256) {
        int r = i >> 5, c8 = (i & 31) * 8;
        *(uint4*)(sW + r * LDW + c8) = *(const uint4*)(wsrc + r * CIN + c8);
    }

    for (int t = 0; t < TG4; ++t) {
        const int row0 = (g * TG4 + t) * 64;
        const __half* abase = g_ah + ((size_t)(b * N + row0)) * KEXT;

        wmma::fragment<wmma::accumulator, 16, 16, 16, float> c[4];
#pragma unroll
        for (int f = 0; f < 4; ++f) wmma::fill_fragment(c[f], 0.0f);

        for (int kt = 0; kt < KEXT; kt += 64) {
            int ktw = kt & (CIN - 1);
            __syncthreads();
#pragma unroll
            for (int l = 0; l < 2; ++l) {
                int idx = tid + l * 256;
                int r = idx >> 3, c8 = (idx & 7) * 8;
                *(uint4*)(sA + r * LDA + c8) = *(const uint4*)(abase + (size_t)r * KEXT + kt + c8);
            }
            __syncthreads();
#pragma unroll
            for (int ks = 0; ks < 4; ++ks) {
                wmma::fragment<wmma::matrix_a, 16, 16, 16, __half, wmma::row_major> a;
                wmma::load_matrix_sync(a, sA + (wr * 16) * LDA + ks * 16, LDA);
#pragma unroll
                for (int cf = 0; cf < 4; ++cf) {
                    wmma::fragment<wmma::matrix_b, 16, 16, 16, __half, wmma::col_major> bf;
                    wmma::load_matrix_sync(bf, sW + (wc * 64 + cf * 16) * LDW + ktw + ks * 16, LDW);
                    wmma::mma_sync(c[cf], a, bf, c[cf]);
                }
            }
        }
        __syncthreads();
#pragma unroll
        for (int cf = 0; cf < 4; ++cf)
            wmma::store_matrix_sync(sC + (wr * 16) * LDC + wc * 64 + cf * 16, c[cf],
                                    LDC, wmma::mem_row_major);
        __syncthreads();

        for (int idx = tid; idx < 2048; idx += 256) {
            int r = idx >> 5, c4 = (idx & 31) * 4;
            float4 v = *(const float4*)&sC[r * LDC + c4];
            float4 bb = *(const float4*)&bo[o0 + c4];
            v.x += bb.x; v.y += bb.y; v.z += bb.z; v.w += bb.w;
            *(float4*)(out + ((size_t)(b * N + row0 + r)) * COUT + o0 + c4) = v;
        }
        // next tile's first barrier protects sC before sA overwrite
    }
}
// ============ launch ============
extern "C" void kernel_launch(void* const* d_in, const int* in_sizes, int n_in,
                              void* d_out, int out_size)
{
    const float* ux = (const float*)d_in[0];
    const float* Wq = (const float*)d_in[2];
    const float* Wk = (const float*)d_in[3];
    const float* Wv = (const float*)d_in[4];
    const float* Wo = (const float*)d_in[5];
    const float* bo = (const float*)d_in[6];
    float* out = (float*)d_out;

    cudaFuncSetAttribute(k1w, cudaFuncAttributeMaxDynamicSharedMemorySize, SMEM_K1);
    cudaFuncSetAttribute(k4w, cudaFuncAttributeMaxDynamicSharedMemorySize, SMEM_K4);

    k0a<<<256, 256>>>(ux);
    k0w<<<8, 256>>>(Wk, Wv);
    k1w<<<dim3(NG1, H, B), 256, SMEM_K1>>>();
    k2_reduce<<<128, 256>>>();
    k3_wqe<<<dim3(4, H, B), 256>>>(Wq);
    k3_wfin<<<dim3(8, 8, B), 256>>>(Wo);
    k3w<<<64, 256>>>();
    k4w<<<dim3(32, 2, B), 256, SMEM_K4>>>(bo, out);
}